// round 9
// baseline (speedup 1.0000x reference)
#include <cuda_runtime.h>
#include <cuda_fp16.h>
#include <cstdint>

// ---- SMEM layout (bytes): 7 x 32KB unpadded swizzled fp16 tiles + small ----
#define OFF_OUTA 0
#define OFF_OUTB 32768
#define OFF_HA   65536
#define OFF_HB   98304
#define OFF_WIM  131072
#define OFF_W1   163840
#define OFF_W2   196608
#define OFF_C0   229376   // float2 (wz,bi)[128] = 1KB
#define OFF_WF   230400   // float[128]
#define OFF_B12  230912   // float2 (b1,b2)[128] = 1KB
#define SMEM_TOTAL 231936

// ---- device scratch ----
__device__ __half g_WiM[(size_t)128 * 16384];  // per-i swizzled 128x128 fp16 image
__device__ float  g_wz[128 * 128];
__device__ __half g_W1h[16384];                // swizzled image
__device__ __half g_W2h[16384];
__device__ float  g_zT[(size_t)128 * 131072];  // [i][b]

// XOR-swizzled byte offset in a 128x128 fp16 tile (row = 256B)
__host__ __device__ __forceinline__ uint32_t tile_off(int r, int c) {
    return (uint32_t)(r * 256 + ((c * 2) ^ ((r & 7) << 4)));
}

// ---- prologue kernels ----
__global__ void prep_weights(const float* __restrict__ Wi, const float* __restrict__ M,
                             const float* __restrict__ W1, const float* __restrict__ W2) {
    int i = blockIdx.x;
    if (i < 128) {
        const float* Wii = Wi + (size_t)i * 16512;   // 128*129
        for (int v = threadIdx.x; v < 16384; v += blockDim.x) {
            int j = v >> 7, k = v & 127;
            float m = (k == i) ? 0.f : M[k * 128 + i];
            g_WiM[(size_t)i * 16384 + (tile_off(j, k) >> 1)] = __float2half(Wii[j * 129 + k] * m);
        }
        for (int j = threadIdx.x; j < 128; j += blockDim.x)
            g_wz[i * 128 + j] = Wii[j * 129 + 128];
    } else if (i == 128) {
        for (int v = threadIdx.x; v < 16384; v += blockDim.x)
            g_W1h[tile_off(v >> 7, v & 127) >> 1] = __float2half(W1[v]);
    } else {
        for (int v = threadIdx.x; v < 16384; v += blockDim.x)
            g_W2h[tile_off(v >> 7, v & 127) >> 1] = __float2half(W2[v]);
    }
}

__global__ void transpose_z(const float* __restrict__ z, int Bn) {
    __shared__ float t[32][33];
    int b0 = blockIdx.x * 32, i0 = blockIdx.y * 32;
    #pragma unroll
    for (int r = threadIdx.y; r < 32; r += 8)
        t[r][threadIdx.x] = z[(size_t)(b0 + r) * 128 + i0 + threadIdx.x];
    __syncthreads();
    #pragma unroll
    for (int r = threadIdx.y; r < 32; r += 8)
        g_zT[(size_t)(i0 + r) * Bn + b0 + threadIdx.x] = t[threadIdx.x][r];
}

// ---- mma helpers ----
__device__ __forceinline__ void ldsm4(uint32_t addr, uint32_t* r) {
    asm volatile("ldmatrix.sync.aligned.m8n8.x4.shared.b16 {%0,%1,%2,%3},[%4];"
        : "=r"(r[0]), "=r"(r[1]), "=r"(r[2]), "=r"(r[3]) : "r"(addr));
}
__device__ __forceinline__ void mma16816(float* c, const uint32_t* a, const uint32_t* b) {
    asm volatile("mma.sync.aligned.m16n8k16.row.col.f32.f16.f16.f32 "
        "{%0,%1,%2,%3},{%4,%5,%6,%7},{%8,%9},{%0,%1,%2,%3};"
        : "+f"(c[0]), "+f"(c[1]), "+f"(c[2]), "+f"(c[3])
        : "r"(a[0]), "r"(a[1]), "r"(a[2]), "r"(a[3]), "r"(b[0]), "r"(b[1]));
}
__device__ __forceinline__ void cpa16(uint32_t s, const void* g) {
    asm volatile("cp.async.cg.shared.global [%0],[%1],16;" :: "r"(s), "l"(g));
}
#define BARH(id) asm volatile("bar.sync %0, %1;" :: "r"(id), "r"(256) : "memory")

// plain 128x128x128 warp-tile GEMM (no interleave)
__device__ __forceinline__ void gemm8(uint32_t aBase, uint32_t bBase,
                                      int lane, int mrow, int ncol, float acc[2][8][4]) {
    #pragma unroll
    for (int mt = 0; mt < 2; mt++)
        #pragma unroll
        for (int nt = 0; nt < 8; nt++)
            #pragma unroll
            for (int c = 0; c < 4; c++) acc[mt][nt][c] = 0.f;

    const int rA = mrow + (lane & 15);
    const uint32_t rowA0 = aBase + (uint32_t)(rA * 256);
    const uint32_t xorA = (uint32_t)((rA & 7) << 4);
    const uint32_t cA = (lane & 16) ? 16u : 0u;
    const int rB = ncol + (lane & 7) + ((lane & 16) ? 8 : 0);
    const uint32_t rowW = bBase + (uint32_t)(rB * 256);
    const uint32_t xorB = (uint32_t)((lane & 7) << 4);
    const uint32_t cB = (lane & 8) ? 16u : 0u;

    #pragma unroll
    for (int ks = 0; ks < 8; ks++) {
        uint32_t offA = ((uint32_t)(ks * 32) + cA) ^ xorA;
        uint32_t offB = ((uint32_t)(ks * 32) + cB) ^ xorB;
        uint32_t a0[4], a1[4], b[16];
        ldsm4(rowA0 + offA, a0);
        ldsm4(rowA0 + 4096 + offA, a1);
        #pragma unroll
        for (int q = 0; q < 4; q++) ldsm4(rowW + (uint32_t)(q * 4096) + offB, b + 4 * q);
        #pragma unroll
        for (int nt = 0; nt < 8; nt++) {
            const uint32_t* bb = b + (nt >> 1) * 4 + (nt & 1) * 2;
            mma16816(acc[0][nt], a0, bb);
            mma16816(acc[1][nt], a1, bb);
        }
    }
}

// ---- dual-half kernel: 512 threads = 2 independent 8-warp halves, 1 tile each ----
__global__ __launch_bounds__(512, 1)
void gen_dual(const float* __restrict__ x,  const float* __restrict__ bi,
              const float* __restrict__ Wf, const float* __restrict__ bf,
              const float* __restrict__ b1, const float* __restrict__ b2,
              float* __restrict__ out, int Bn, int baseRow)
{
    extern __shared__ char sm[];
    const int tid = threadIdx.x, lane = tid & 31;
    const int h = tid >> 8;                    // half 0/1
    const int wid8 = (tid >> 5) & 7;           // warp within half
    const int wm = wid8 >> 1, wn = wid8 & 1;
    const int mrow = wm * 32, ncol = wn * 64;
    const int gr0 = lane >> 2, gc0 = 2 * (lane & 3);
    const int tl = tid & 255;                  // thread within half
    const int barId = 1 + h;
    const size_t bh = (size_t)baseRow + (size_t)blockIdx.x * 256 + (size_t)(h << 7);

    const uint32_t smBase = (uint32_t)__cvta_generic_to_shared(sm);
    const uint32_t aOutH = smBase + (h ? OFF_OUTB : OFF_OUTA);
    const uint32_t aHH   = smBase + (h ? OFF_HB : OFF_HA);
    const uint32_t aWiM = smBase + OFF_WIM, aW1 = smBase + OFF_W1, aW2 = smBase + OFF_W2;
    char* outT = sm + (h ? OFF_OUTB : OFF_OUTA);
    char* hT   = sm + (h ? OFF_HB : OFF_HA);
    float* sO2 = (float*)hT;                   // stash: H tile dead during E2 finalize
    float2* sC0  = (float2*)(sm + OFF_C0);
    float*  sWf  = (float*)(sm + OFF_WF);
    float2* sB12 = (float2*)(sm + OFF_B12);

    // ---- stage x into both tiles ----
    const float4* xg = (const float4*)(x + ((size_t)baseRow + (size_t)blockIdx.x * 256) * 128);
    #pragma unroll
    for (int q = 0; q < 16; q++) {
        int v = (q << 9) + tid;                // 0..8191 float4
        float4 f = xg[v];
        int rv = v >> 5, c4 = (v & 31) << 2;
        uint32_t off = tile_off(rv & 127, c4);
        char* base = sm + ((rv >> 7) ? OFF_OUTB : OFF_OUTA);
        *(__half2*)(base + off)     = __floats2half2_rn(f.x, f.y);
        *(__half2*)(base + off + 4) = __floats2half2_rn(f.z, f.w);
    }
    #pragma unroll
    for (int q = 0; q < 4; q++) {
        int v = (q << 9) + tid;
        ((uint4*)(sm + OFF_W1))[v] = ((const uint4*)g_W1h)[v];
        ((uint4*)(sm + OFF_W2))[v] = ((const uint4*)g_W2h)[v];
        cpa16(aWiM + (uint32_t)(v << 4), ((const uint4*)g_WiM) + v);
    }
    asm volatile("cp.async.commit_group;");
    if (tid < 128) sB12[tid] = make_float2(b1[tid], b2[tid]);
    asm volatile("cp.async.wait_group 0;");
    __syncthreads();

    float acc[2][8][4];

    for (int i = 0; i < 128; i++) {
        if (i) asm volatile("cp.async.wait_group 0;");
        __syncthreads();                       // S_pre: WiM(i) + prev OUT writes visible

        // stage per-step coefficients (both halves cooperate; visible after S_post)
        if (tid < 128)      sC0[tid] = make_float2(g_wz[(i << 7) + tid], bi[(i << 7) + tid]);
        else if (tid < 256) sWf[tid - 128] = Wf[(i << 7) + tid - 128];
        const float bfi = bf[i];
        const float* zg = g_zT + (size_t)i * Bn + bh;

        // ---- G0: h1_pre = OUT_h @ WiM^T ----
        gemm8(aOutH, aWiM, lane, mrow, ncol, acc);
        __syncthreads();                       // S_post: WiM reads done; coeffs visible
        if (i < 127) {                         // prefetch WiM(i+1), all 512 threads
            const uint4* src = (const uint4*)(g_WiM + (size_t)(i + 1) * 16384);
            #pragma unroll
            for (int q = 0; q < 4; q++) {
                int v = (q << 9) + tid;
                cpa16(aWiM + (uint32_t)(v << 4), src + v);
            }
            asm volatile("cp.async.commit_group;");
        }

        // ---- E0: h1 = relu(pre + z*wz + bi) -> H_h ----
        {
            const int zr = mrow + gr0;
            const float z0 = zg[zr], z1 = zg[zr + 8], z2 = zg[zr + 16], z3 = zg[zr + 24];
            const uint32_t xrE = (uint32_t)(gr0 << 4);
            #pragma unroll
            for (int nt = 0; nt < 8; nt++) {
                const int c = ncol + nt * 8 + gc0;
                float2 t0 = sC0[c], t1 = sC0[c + 1];
                const uint32_t cb = ((uint32_t)(2 * c)) ^ xrE;
                #pragma unroll
                for (int mt = 0; mt < 2; mt++) {
                    const int r0 = mrow + mt * 16 + gr0, r1 = r0 + 8;
                    const float zlo = mt ? z2 : z0, zhi = mt ? z3 : z1;
                    float v00 = fmaxf(fmaf(zlo, t0.x, acc[mt][nt][0]) + t0.y, 0.f);
                    float v01 = fmaxf(fmaf(zlo, t1.x, acc[mt][nt][1]) + t1.y, 0.f);
                    float v10 = fmaxf(fmaf(zhi, t0.x, acc[mt][nt][2]) + t0.y, 0.f);
                    float v11 = fmaxf(fmaf(zhi, t1.x, acc[mt][nt][3]) + t1.y, 0.f);
                    *(__half2*)(hT + r0 * 256 + cb) = __floats2half2_rn(v00, v01);
                    *(__half2*)(hT + r1 * 256 + cb) = __floats2half2_rn(v10, v11);
                }
            }
        }
        BARH(barId);                           // H_h ready for G1 (this half only)

        // ---- G1: h2_pre = H_h @ W1^T ----
        gemm8(aHH, aW1, lane, mrow, ncol, acc);
        BARH(barId);                           // G1 H reads done before E1 overwrite

        // ---- E1: h2 = relu(pre + b1) -> H_h ----
        {
            const uint32_t xrE = (uint32_t)(gr0 << 4);
            #pragma unroll
            for (int nt = 0; nt < 8; nt++) {
                const int c = ncol + nt * 8 + gc0;
                const float q0 = sB12[c].x, q1 = sB12[c + 1].x;
                const uint32_t cb = ((uint32_t)(2 * c)) ^ xrE;
                #pragma unroll
                for (int mt = 0; mt < 2; mt++) {
                    const int r0 = mrow + mt * 16 + gr0, r1 = r0 + 8;
                    float v00 = fmaxf(acc[mt][nt][0] + q0, 0.f);
                    float v01 = fmaxf(acc[mt][nt][1] + q1, 0.f);
                    float v10 = fmaxf(acc[mt][nt][2] + q0, 0.f);
                    float v11 = fmaxf(acc[mt][nt][3] + q1, 0.f);
                    *(__half2*)(hT + r0 * 256 + cb) = __floats2half2_rn(v00, v01);
                    *(__half2*)(hT + r1 * 256 + cb) = __floats2half2_rn(v10, v11);
                }
            }
        }
        BARH(barId);                           // H_h(h2) ready for G2

        // ---- G2: h3_pre = H_h @ W2^T ----
        gemm8(aHH, aW2, lane, mrow, ncol, acc);

        // ---- E2: o = relu(pre + b2) @ Wf + bf ----
        float p[2][2] = {{0.f, 0.f}, {0.f, 0.f}};
        #pragma unroll
        for (int nt = 0; nt < 8; nt++) {
            const int c = ncol + nt * 8 + gc0;
            const float wf0 = sWf[c], wf1 = sWf[c + 1];
            const float q0 = sB12[c].y, q1 = sB12[c + 1].y;
            #pragma unroll
            for (int mt = 0; mt < 2; mt++) {
                p[mt][0] = fmaf(fmaxf(acc[mt][nt][0] + q0, 0.f), wf0,
                           fmaf(fmaxf(acc[mt][nt][1] + q1, 0.f), wf1, p[mt][0]));
                p[mt][1] = fmaf(fmaxf(acc[mt][nt][2] + q0, 0.f), wf0,
                           fmaf(fmaxf(acc[mt][nt][3] + q1, 0.f), wf1, p[mt][1]));
            }
        }
        BARH(barId);                           // all G2 H_h reads done -> sO2 stash safe
        #pragma unroll
        for (int mt = 0; mt < 2; mt++)
            #pragma unroll
            for (int hh = 0; hh < 2; hh++) {
                float v = p[mt][hh];
                v += __shfl_xor_sync(0xffffffffu, v, 1);
                v += __shfl_xor_sync(0xffffffffu, v, 2);
                if ((lane & 3) == 0)
                    sO2[wn * 128 + mrow + mt * 16 + hh * 8 + gr0] = v;
            }
        BARH(barId);
        if (tl < 128) {
            float o = sO2[tl] + sO2[128 + tl] + bfi;
            out[(bh + tl) * 128 + i] = o;
            *(__half*)(outT + tile_off(tl, i)) = __float2half(o);
        }
        // next-iteration S_pre orders OUT_h writes before G0 reads
    }
}

// ---- single-tile kernel (leftover wave, 256 threads) ----
__global__ __launch_bounds__(256, 1)
void gen_single(const float* __restrict__ x,  const float* __restrict__ bi,
                const float* __restrict__ Wf, const float* __restrict__ bf,
                const float* __restrict__ b1, const float* __restrict__ b2,
                float* __restrict__ out, int Bn, int baseRow)
{
    extern __shared__ char sm[];
    const int tid = threadIdx.x, lane = tid & 31, wid = tid >> 5;
    const int wm = wid >> 1, wn = wid & 1;
    const int mrow = wm * 32, ncol = wn * 64;
    const int gr0 = lane >> 2, gc0 = 2 * (lane & 3);
    const size_t b0 = (size_t)baseRow + (size_t)blockIdx.x * 128;

    const uint32_t smBase = (uint32_t)__cvta_generic_to_shared(sm);
    const uint32_t aOutA = smBase + OFF_OUTA;
    const uint32_t aHA = smBase + OFF_HA;
    const uint32_t aWiM = smBase + OFF_WIM, aW1 = smBase + OFF_W1, aW2 = smBase + OFF_W2;
    char* hA = sm + OFF_HA;
    float2* sC0  = (float2*)(sm + OFF_C0);
    float*  sO2  = (float*)(sm + OFF_C0);
    float*  sWf  = (float*)(sm + OFF_WF);
    float2* sB12 = (float2*)(sm + OFF_B12);

    const float4* xg = (const float4*)(x + b0 * 128);
    #pragma unroll
    for (int q = 0; q < 16; q++) {
        int v = (q << 8) + tid;
        float4 f = xg[v];
        int rv = v >> 5, c4 = (v & 31) << 2;
        uint32_t off = tile_off(rv & 127, c4);
        *(__half2*)(sm + OFF_OUTA + off)     = __floats2half2_rn(f.x, f.y);
        *(__half2*)(sm + OFF_OUTA + off + 4) = __floats2half2_rn(f.z, f.w);
    }
    #pragma unroll
    for (int q = 0; q < 8; q++) {
        int v = (q << 8) + tid;
        ((uint4*)(sm + OFF_W1))[v] = ((const uint4*)g_W1h)[v];
        ((uint4*)(sm + OFF_W2))[v] = ((const uint4*)g_W2h)[v];
        cpa16(aWiM + (uint32_t)(v << 4), ((const uint4*)g_WiM) + v);
    }
    asm volatile("cp.async.commit_group;");
    if (tid < 128) sB12[tid] = make_float2(b1[tid], b2[tid]);
    asm volatile("cp.async.wait_group 0;");
    __syncthreads();

    float accA[2][8][4];

    for (int i = 0; i < 128; i++) {
        if (tid < 128) {
            sC0[tid] = make_float2(g_wz[(i << 7) + tid], bi[(i << 7) + tid]);
            sWf[tid] = Wf[(i << 7) + tid];
        }
        const float bfi = bf[i];
        const float* zg = g_zT + (size_t)i * Bn + b0;
        const int zr = mrow + gr0;
        float zA0 = zg[zr], zA1 = zg[zr + 8], zA2 = zg[zr + 16], zA3 = zg[zr + 24];
        __syncthreads();

        gemm8(aOutA, aWiM, lane, mrow, ncol, accA);
        __syncthreads();
        if (i < 127) {
            const uint4* src = (const uint4*)(g_WiM + (size_t)(i + 1) * 16384);
            #pragma unroll
            for (int q = 0; q < 8; q++) {
                int v = (q << 8) + tid;
                cpa16(aWiM + (uint32_t)(v << 4), src + v);
            }
            asm volatile("cp.async.commit_group;");
        }
        {
            const uint32_t xrE = (uint32_t)(gr0 << 4);
            #pragma unroll
            for (int nt = 0; nt < 8; nt++) {
                const int c = ncol + nt * 8 + gc0;
                float2 t0 = sC0[c], t1 = sC0[c + 1];
                const uint32_t cb = ((uint32_t)(2 * c)) ^ xrE;
                #pragma unroll
                for (int mt = 0; mt < 2; mt++) {
                    const int r0 = mrow + mt * 16 + gr0, r1 = r0 + 8;
                    const float zlo = mt ? zA2 : zA0, zhi = mt ? zA3 : zA1;
                    float v00 = fmaxf(fmaf(zlo, t0.x, accA[mt][nt][0]) + t0.y, 0.f);
                    float v01 = fmaxf(fmaf(zlo, t1.x, accA[mt][nt][1]) + t1.y, 0.f);
                    float v10 = fmaxf(fmaf(zhi, t0.x, accA[mt][nt][2]) + t0.y, 0.f);
                    float v11 = fmaxf(fmaf(zhi, t1.x, accA[mt][nt][3]) + t1.y, 0.f);
                    *(__half2*)(hA + r0 * 256 + cb) = __floats2half2_rn(v00, v01);
                    *(__half2*)(hA + r1 * 256 + cb) = __floats2half2_rn(v10, v11);
                }
            }
        }
        __syncthreads();
        gemm8(aHA, aW1, lane, mrow, ncol, accA);
        __syncthreads();
        {
            const uint32_t xrE = (uint32_t)(gr0 << 4);
            #pragma unroll
            for (int nt = 0; nt < 8; nt++) {
                const int c = ncol + nt * 8 + gc0;
                float q0 = sB12[c].x, q1 = sB12[c + 1].x;
                const uint32_t cb = ((uint32_t)(2 * c)) ^ xrE;
                #pragma unroll
                for (int mt = 0; mt < 2; mt++) {
                    const int r0 = mrow + mt * 16 + gr0, r1 = r0 + 8;
                    float v00 = fmaxf(accA[mt][nt][0] + q0, 0.f);
                    float v01 = fmaxf(accA[mt][nt][1] + q1, 0.f);
                    float v10 = fmaxf(accA[mt][nt][2] + q0, 0.f);
                    float v11 = fmaxf(accA[mt][nt][3] + q1, 0.f);
                    *(__half2*)(hA + r0 * 256 + cb) = __floats2half2_rn(v00, v01);
                    *(__half2*)(hA + r1 * 256 + cb) = __floats2half2_rn(v10, v11);
                }
            }
        }
        __syncthreads();
        gemm8(aHA, aW2, lane, mrow, ncol, accA);
        {
            float p[2][2] = {{0.f, 0.f}, {0.f, 0.f}};
            #pragma unroll
            for (int nt = 0; nt < 8; nt++) {
                const int c = ncol + nt * 8 + gc0;
                const float wf0 = sWf[c], wf1 = sWf[c + 1];
                const float q0 = sB12[c].y, q1 = sB12[c + 1].y;
                #pragma unroll
                for (int mt = 0; mt < 2; mt++) {
                    p[mt][0] = fmaf(fmaxf(accA[mt][nt][0] + q0, 0.f), wf0,
                               fmaf(fmaxf(accA[mt][nt][1] + q1, 0.f), wf1, p[mt][0]));
                    p[mt][1] = fmaf(fmaxf(accA[mt][nt][2] + q0, 0.f), wf0,
                               fmaf(fmaxf(accA[mt][nt][3] + q1, 0.f), wf1, p[mt][1]));
                }
            }
            __syncthreads();
            #pragma unroll
            for (int mt = 0; mt < 2; mt++)
                #pragma unroll
                for (int hh = 0; hh < 2; hh++) {
                    float v = p[mt][hh];
                    v += __shfl_xor_sync(0xffffffffu, v, 1);
                    v += __shfl_xor_sync(0xffffffffu, v, 2);
                    if ((lane & 3) == 0)
                        sO2[wn * 128 + mrow + mt * 16 + hh * 8 + gr0] = v;
                }
            __syncthreads();
            if (tid < 128) {
                float o = sO2[tid] + sO2[128 + tid] + bfi;
                out[(b0 + tid) * 128 + i] = o;
                *(__half*)(sm + OFF_OUTA + tile_off(tid, i)) = __float2half(o);
            }
        }
        if (i < 127) asm volatile("cp.async.wait_group 0;");
        __syncthreads();
    }
}

// ---- host ----
extern "C" void kernel_launch(void* const* d_in, const int* in_sizes, int n_in,
                              void* d_out, int out_size) {
    const float* x  = (const float*)d_in[0];
    const float* z  = (const float*)d_in[1];
    const float* M  = (const float*)d_in[2];
    const float* Wi = (const float*)d_in[3];
    const float* bi = (const float*)d_in[4];
    const float* Wf = (const float*)d_in[5];
    const float* bf = (const float*)d_in[6];
    const float* W1 = (const float*)d_in[7];
    const float* b1 = (const float*)d_in[8];
    const float* W2 = (const float*)d_in[9];
    const float* b2 = (const float*)d_in[10];
    int Bn = in_sizes[0] / 128;

    cudaFuncSetAttribute(gen_dual,   cudaFuncAttributeMaxDynamicSharedMemorySize, SMEM_TOTAL);
    cudaFuncSetAttribute(gen_single, cudaFuncAttributeMaxDynamicSharedMemorySize, SMEM_TOTAL);

    prep_weights<<<130, 256>>>(Wi, M, W1, W2);
    transpose_z<<<dim3(Bn / 32, 4), dim3(32, 8)>>>(z, Bn);

    int tiles = Bn / 128;                       // 1024
    int nPair = ((tiles / 2) / 148) * 148;      // 444 (3 full waves)
    int nSingle = tiles - 2 * nPair;            // 136 (1 partial wave)
    if (nPair > 0)
        gen_dual<<<nPair, 512, SMEM_TOTAL>>>(x, bi, Wf, bf, b1, b2, (float*)d_out, Bn, 0);
    if (nSingle > 0)
        gen_single<<<nSingle, 256, SMEM_TOTAL>>>(x, bi, Wf, bf, b1, b2, (float*)d_out, Bn, nPair * 256);
}